// round 15
// baseline (speedup 1.0000x reference)
#include <cuda_runtime.h>
#include <cuda_fp16.h>
#include <math.h>
#include <stdint.h>

// Problem constants
#define TT 2048
#define HH 2048
#define II 1792
#define EE 16
#define TOPK 4
#define RR (TT*TOPK)

// ---------------- scratch ----------------
__device__ __half d_xh[(size_t)TT * HH];
__device__ __half d_ACTh[(size_t)RR * II];
__device__ float d_Y[(size_t)RR * HH];
__device__ __half d_g16[(size_t)EE * HH * II];
__device__ __half d_u16[(size_t)EE * HH * II];
__device__ __half d_d16[(size_t)EE * II * HH];
__device__ int   d_counts[EE];
__device__ int   d_offsets[EE];
__device__ int   d_cursors[EE];
__device__ int   d_rows[RR];
__device__ int   d_posof[TT * TOPK];
__device__ float d_topw[TT * TOPK];
__device__ int   d_topi[TT * TOPK];
__device__ int   d_actDone[EE];   // gemm0 blocks completed per expert
__device__ int   d_yDone[EE];     // gemm1 blocks completed per expert

// ---------------- helpers ----------------
__device__ __forceinline__ uint32_t smem_u32(const void* p) {
    return (uint32_t)__cvta_generic_to_shared(p);
}
__device__ __forceinline__ void ldsm_x4(uint32_t* r, uint32_t addr) {
    asm volatile("ldmatrix.sync.aligned.m8n8.x4.shared.b16 {%0,%1,%2,%3}, [%4];"
                 : "=r"(r[0]), "=r"(r[1]), "=r"(r[2]), "=r"(r[3]) : "r"(addr));
}
__device__ __forceinline__ void ldsm_x4t(uint32_t* r, uint32_t addr) {
    asm volatile("ldmatrix.sync.aligned.m8n8.x4.trans.shared.b16 {%0,%1,%2,%3}, [%4];"
                 : "=r"(r[0]), "=r"(r[1]), "=r"(r[2]), "=r"(r[3]) : "r"(addr));
}
__device__ __forceinline__ void mma_f16(float* d, const uint32_t* a, const uint32_t* b) {
    asm volatile("mma.sync.aligned.m16n8k16.row.col.f32.f16.f16.f32 "
                 "{%0,%1,%2,%3}, {%4,%5,%6,%7}, {%8,%9}, {%0,%1,%2,%3};"
                 : "+f"(d[0]), "+f"(d[1]), "+f"(d[2]), "+f"(d[3])
                 : "r"(a[0]), "r"(a[1]), "r"(a[2]), "r"(a[3]), "r"(b[0]), "r"(b[1]));
}
__device__ __forceinline__ void cp16(uint32_t dst, const void* src, bool valid) {
    int sz = valid ? 16 : 0;
    asm volatile("cp.async.cg.shared.global [%0], [%1], 16, %2;"
                 :: "r"(dst), "l"(src), "r"(sz));
}
__device__ __forceinline__ void cp_commit() {
    asm volatile("cp.async.commit_group;" ::: "memory");
}
__device__ __forceinline__ void cp_wait1() {
    asm volatile("cp.async.wait_group 1;" ::: "memory");
}
__device__ __forceinline__ void cp_wait0() {
    asm volatile("cp.async.wait_group 0;" ::: "memory");
}
__device__ __forceinline__ uint32_t pack2h(float a, float b) {
    __half2 p = __halves2half2(__float2half(a), __float2half(b));
    return *(uint32_t*)&p;
}
__device__ __forceinline__ void conv_f4(const float4* src, uint2* dst, size_t i) {
    float4 v = src[i];
    uint2 h;
    h.x = pack2h(v.x, v.y);
    h.y = pack2h(v.z, v.w);
    dst[i] = h;
}
// producer: all stores visible at GPU scope, then one increment
__device__ __forceinline__ void signal_counter(int* ctr) {
    __threadfence();
    __syncthreads();
    if (threadIdx.x == 0) atomicAdd(ctr, 1);
}
// consumer: block until counter reaches target
__device__ __forceinline__ void wait_counter(int* ctr, int target) {
    if (threadIdx.x == 0) {
        while (*(volatile int*)ctr < target) __nanosleep(200);
    }
    __syncthreads();
    __threadfence();
}

// ---------------- routing ----------------
__global__ void zero_counts_kernel() {
    if (threadIdx.x < EE) {
        d_counts[threadIdx.x] = 0;
        d_actDone[threadIdx.x] = 0;
        d_yDone[threadIdx.x] = 0;
    }
}

// Fused prep: router (blocks [0,256)) + x->fp16 (blocks [256,1280))
//           + gate/up weights->fp16 (blocks [1280,5376))
#define PREP_ROUTER 256
#define PREP_CONVX  1024
#define PREP_CONVW  4096
#define PREP_GRID   (PREP_ROUTER + PREP_CONVX + PREP_CONVW)
__global__ __launch_bounds__(256)
void prep_kernel(const float* __restrict__ x,
                 const float* __restrict__ rw,
                 const float* __restrict__ bias,
                 const float* __restrict__ gate,
                 const float* __restrict__ up) {
    int b = blockIdx.x;
    if (b >= PREP_ROUTER + PREP_CONVX) {
        int c = b - PREP_ROUTER - PREP_CONVX;
        const float4* src;
        uint2* dst;
        size_t base;
        if (c < PREP_CONVW / 2) {
            src = (const float4*)gate; dst = (uint2*)d_g16;
            base = (size_t)c * 7168;
        } else {
            src = (const float4*)up; dst = (uint2*)d_u16;
            base = (size_t)(c - PREP_CONVW / 2) * 7168;
        }
#pragma unroll
        for (int i = 0; i < 28; i++)
            conv_f4(src, dst, base + threadIdx.x + 256 * i);
        return;
    }
    if (b >= PREP_ROUTER) {
        size_t base = (size_t)(b - PREP_ROUTER) * 1024;
#pragma unroll
        for (int i = 0; i < 4; i++)
            conv_f4((const float4*)x, (uint2*)d_xh, base + threadIdx.x + 256 * i);
        return;
    }
    // --- router: warp per token ---
    int warp = (b * blockDim.x + threadIdx.x) >> 5;
    int lane = threadIdx.x & 31;
    const float* xr = x + (size_t)warp * HH;
    float acc[EE];
#pragma unroll
    for (int e = 0; e < EE; e++) acc[e] = 0.f;
    for (int h = lane; h < HH; h += 32) {
        float xv = __ldg(xr + h);
#pragma unroll
        for (int e = 0; e < EE; e++) acc[e] += xv * __ldg(rw + (size_t)e * HH + h);
    }
#pragma unroll
    for (int e = 0; e < EE; e++) {
        float v = acc[e];
#pragma unroll
        for (int o = 16; o > 0; o >>= 1) v += __shfl_xor_sync(0xffffffffu, v, o);
        acc[e] = v + bias[e];
    }
    if (lane == 0) {
        int idx[TOPK]; float lg[TOPK];
        unsigned used = 0;
        for (int k = 0; k < TOPK; k++) {
            float best = -INFINITY; int bi = 0;
            for (int e = 0; e < EE; e++) {
                if ((used >> e) & 1u) continue;
                if (acc[e] > best) { best = acc[e]; bi = e; }
            }
            used |= 1u << bi; idx[k] = bi; lg[k] = best;
        }
        float mx = lg[0], w[TOPK], s = 0.f;
        for (int k = 0; k < TOPK; k++) { w[k] = expf(lg[k] - mx); s += w[k]; }
        float inv = 1.f / s;
        for (int k = 0; k < TOPK; k++) {
            d_topi[warp * TOPK + k] = idx[k];
            d_topw[warp * TOPK + k] = w[k] * inv;
            atomicAdd(&d_counts[idx[k]], 1);
        }
    }
}

__global__ void scan_kernel() {
    int off = 0;
    for (int e = 0; e < EE; e++) { d_offsets[e] = off; d_cursors[e] = off; off += d_counts[e]; }
}

__global__ void assign_kernel() {
    int t = blockIdx.x * blockDim.x + threadIdx.x;
    if (t >= TT) return;
    for (int k = 0; k < TOPK; k++) {
        int e = d_topi[t * TOPK + k];
        int pos = atomicAdd(&d_cursors[e], 1);
        d_rows[pos] = t;
        d_posof[t * TOPK + k] = pos;
    }
}

// ---------------- GEMM body (fp16 mma.sync, 3-stage cp.async, BK=64) ----------------
#define BK 64
#define S_A    0          // 128 rows x 144B = 18432
#define S_B0   18432      // 64 k-rows x 144B = 9216
#define S_B1   27648
#define STAGE_BYTES 36864
#define NSTAGE 3
#define SM_STAGE0 1024
#define SMEM_TOTAL (SM_STAGE0 + NSTAGE*STAGE_BYTES)   // 111616 -> 2 CTAs/SM

#define MT 8            // m-tiles per expert
#define NB0 (28*MT*EE)  // 3584 gemm0 blocks (expert-major)
#define NB1 (16*MT*EE)  // 2048 gemm1 blocks (expert-major)
#define NBC TT          // 2048 combine blocks

template<int MODE>
__device__ __forceinline__ void gemm_body(char* sm, int e, int mblk, int nb)
{
    constexpr int Kd  = (MODE == 0) ? HH : II;
    constexpr int ldB = (MODE == 0) ? II : HH;
    constexpr int NK  = Kd / BK;

    int tid = threadIdx.x, wid = tid >> 5, lane = tid & 31;
    int cnt = d_counts[e];
    int off = d_offsets[e];

    const __half* B0; const __half* B1;
    if (MODE == 0) {
        B0 = d_g16 + (size_t)e * HH * II + nb;
        B1 = d_u16 + (size_t)e * HH * II + nb;
    } else {
        B0 = d_d16 + (size_t)e * II * HH + nb;
        B1 = B0 + 64;
    }
    const __half* srcH = (MODE == 0) ? d_xh : d_ACTh;

    // cache gathered row indices (-1 = invalid)
    int* rowIdx = (int*)sm;
    if (tid < 128) {
        int lr = mblk * 128 + tid;
        int r = -1;
        if (lr < cnt) r = (MODE == 0) ? d_rows[off + lr] : (off + lr);
        rowIdx[tid] = r;
    }
    __syncthreads();

    uint32_t smb = smem_u32(sm);

    auto load_stage = [&](int s, int kc) {
        uint32_t sb = smb + SM_STAGE0 + s * STAGE_BYTES;
#pragma unroll
        for (int i = 0; i < 4; i++) {
            int slot = tid + 256 * i;
            int row = slot >> 3, seg = slot & 7;
            int r = rowIdx[row];
            bool v = r >= 0;
            size_t go = (size_t)(v ? r : 0) * Kd + kc * BK + seg * 8;
            cp16(sb + S_A + row * 144 + seg * 16, srcH + go, v);
        }
#pragma unroll
        for (int i = 0; i < 4; i++) {
            int slot = tid + 256 * i;
            int mat = slot >> 9, rem = slot & 511;
            int row = rem >> 3, seg = rem & 7;
            const __half* src = (mat ? B1 : B0) + (size_t)(kc * BK + row) * ldB + seg * 8;
            cp16(sb + (mat ? S_B1 : S_B0) + row * 144 + seg * 16, src, true);
        }
        cp_commit();
    };

    int wm = wid & 3, wn = wid >> 2;
    int sub = lane >> 3, lr = lane & 7;
    int a_row0 = wm * 32 + ((sub & 1) << 3) + lr;
    int a_kc   = (sub >> 1) << 3;
    int b_krow = (((lane >> 3) & 1) << 3) + lr;
    int b_nc0  = wn * 32;
    int b_cx   = (lane >> 4) << 3;

    float acc0[2][4][4], acc1[2][4][4];
#pragma unroll
    for (int i = 0; i < 2; i++)
#pragma unroll
        for (int j = 0; j < 4; j++)
#pragma unroll
            for (int c = 0; c < 4; c++) { acc0[i][j][c] = 0.f; acc1[i][j][c] = 0.f; }

    auto mma_stage = [&](int s) {
        uint32_t sb = smb + SM_STAGE0 + s * STAGE_BYTES;
#pragma unroll
        for (int ck = 0; ck < 4; ck++) {
            uint32_t ah[2][4];
#pragma unroll
            for (int am = 0; am < 2; am++) {
                int row = a_row0 + am * 16;
                int col = ck * 16 + a_kc;
                ldsm_x4(ah[am], sb + S_A + row * 144 + col * 2);
            }
            {
                uint32_t bh[4][2];
#pragma unroll
                for (int an = 0; an < 4; an += 2) {
                    int krow = ck * 16 + b_krow;
                    int ncol = b_nc0 + an * 8 + b_cx;
                    ldsm_x4t(&bh[an][0], sb + S_B0 + krow * 144 + ncol * 2);
                }
#pragma unroll
                for (int am = 0; am < 2; am++)
#pragma unroll
                    for (int an = 0; an < 4; an++)
                        mma_f16(acc0[am][an], ah[am], bh[an]);
            }
            {
                uint32_t bh[4][2];
#pragma unroll
                for (int an = 0; an < 4; an += 2) {
                    int krow = ck * 16 + b_krow;
                    int ncol = b_nc0 + an * 8 + b_cx;
                    ldsm_x4t(&bh[an][0], sb + S_B1 + krow * 144 + ncol * 2);
                }
#pragma unroll
                for (int am = 0; am < 2; am++)
#pragma unroll
                    for (int an = 0; an < 4; an++)
                        mma_f16(acc1[am][an], ah[am], bh[an]);
            }
        }
    };

    load_stage(0, 0);
    load_stage(1, 1);
    for (int kc = 0; kc < NK; kc++) {
        if (kc + 1 == NK) cp_wait0(); else cp_wait1();
        __syncthreads();
        if (kc + 2 < NK) load_stage((kc + 2) % NSTAGE, kc + 2);
        mma_stage(kc % NSTAGE);
    }

    // epilogue
    int lrow = lane >> 2;
    int lcol = (lane & 3) << 1;
#pragma unroll
    for (int am = 0; am < 2; am++) {
#pragma unroll
        for (int hf = 0; hf < 2; hf++) {
            int row = wm * 32 + am * 16 + hf * 8 + lrow;
            int gm = mblk * 128 + row;
            if (gm >= cnt) continue;
            if (MODE == 0) {
                size_t base = (size_t)(off + gm) * II + nb + wn * 32 + lcol;
#pragma unroll
                for (int an = 0; an < 4; an++) {
                    float g0 = acc0[am][an][hf * 2],     u0 = acc1[am][an][hf * 2];
                    float g1 = acc0[am][an][hf * 2 + 1], u1 = acc1[am][an][hf * 2 + 1];
                    float a0 = g0 / (1.f + expf(-g0)) * u0;
                    float a1 = g1 / (1.f + expf(-g1)) * u1;
                    *(uint32_t*)&d_ACTh[base + an * 8] = pack2h(a0, a1);
                }
            } else {
                size_t base = (size_t)(off + gm) * HH + nb + wn * 32 + lcol;
#pragma unroll
                for (int an = 0; an < 4; an++) {
                    *(float2*)&d_Y[base + an * 8] =
                        make_float2(acc0[am][an][hf * 2], acc0[am][an][hf * 2 + 1]);
                    *(float2*)&d_Y[base + 64 + an * 8] =
                        make_float2(acc1[am][an][hf * 2], acc1[am][an][hf * 2 + 1]);
                }
            }
        }
    }
}

// ---------------- MEGA kernel: gemm0 (+down-conv) | gemm1 | combine ----------------
__global__ __launch_bounds__(256, 2)
void mega_kernel(const float* __restrict__ downW, float* __restrict__ out)
{
    extern __shared__ __align__(16) char sm[];
    int b = blockIdx.x;
    int tid = threadIdx.x;

    if (b < NB0) {
        // ---- gemm0 (expert-major) + this expert's down-weight slice conversion ----
        int e = b / (28 * MT);
        int rem = b % (28 * MT);
        int mblk = rem / 28;
        int nb = (rem % 28) * 64;
        // convert expert e's down slice: 224 blocks x 4096 float4 = II*HH/4 exactly
        {
            size_t base = (size_t)e * ((size_t)II * HH / 4) + (size_t)rem * 4096;
#pragma unroll
            for (int i = 0; i < 16; i++)
                conv_f4((const float4*)downW, (uint2*)d_d16, base + tid + 256 * i);
        }
        if (mblk * 128 < d_counts[e]) {
            gemm_body<0>(sm, e, mblk, nb);
        }
        signal_counter(&d_actDone[e]);
        return;
    }
    if (b < NB0 + NB1) {
        // ---- gemm1 (expert-major); waits for all gemm0 blocks of this expert ----
        int c = b - NB0;
        int e = c / (16 * MT);
        int rem = c % (16 * MT);
        int mblk = rem / 16;
        int nb = (rem % 16) * 128;
        wait_counter(&d_actDone[e], 28 * MT);
        if (mblk * 128 < d_counts[e]) {
            gemm_body<1>(sm, e, mblk, nb);
        }
        signal_counter(&d_yDone[e]);
        return;
    }
    // ---- combine: one block per token; waits for its 4 experts' gemm1 ----
    int t = b - NB0 - NB1;
    if (tid == 0) {
#pragma unroll
        for (int k = 0; k < TOPK; k++) {
            int e = d_topi[t * TOPK + k];
            while (*(volatile int*)&d_yDone[e] < 16 * MT) __nanosleep(200);
        }
    }
    __syncthreads();
    __threadfence();
    float w[TOPK]; int p[TOPK];
#pragma unroll
    for (int k = 0; k < TOPK; k++) {
        w[k] = d_topw[t * TOPK + k];
        p[k] = d_posof[t * TOPK + k];
    }
    for (int h = tid * 4; h < HH; h += 256 * 4) {
        float4 s = make_float4(0, 0, 0, 0);
#pragma unroll
        for (int k = 0; k < TOPK; k++) {
            float4 y = __ldcg((const float4*)&d_Y[(size_t)p[k] * HH + h]);
            s.x += w[k] * y.x; s.y += w[k] * y.y;
            s.z += w[k] * y.z; s.w += w[k] * y.w;
        }
        *(float4*)&out[(size_t)t * HH + h] = s;
    }
}

// ---------------- launch ----------------
extern "C" void kernel_launch(void* const* d_in, const int* in_sizes, int n_in,
                              void* d_out, int out_size) {
    const float* x    = (const float*)d_in[0];
    const float* rw   = (const float*)d_in[1];
    const float* bias = (const float*)d_in[2];
    const float* gate = (const float*)d_in[3];
    const float* up   = (const float*)d_in[4];
    const float* down = (const float*)d_in[5];
    float* out = (float*)d_out;

    cudaFuncSetAttribute(mega_kernel, cudaFuncAttributeMaxDynamicSharedMemorySize, SMEM_TOTAL);

    zero_counts_kernel<<<1, 32>>>();
    prep_kernel<<<PREP_GRID, 256>>>(x, rw, bias, gate, up);
    scan_kernel<<<1, 1>>>();
    assign_kernel<<<TT / 256, 256>>>();
    mega_kernel<<<NB0 + NB1 + NBC, 256, SMEM_TOTAL>>>(down, out);
}